// round 8
// baseline (speedup 1.0000x reference)
#include <cuda_runtime.h>
#include <cuda_bf16.h>

#define SDIM 128
#define CDIM 8
#define ROWS_PER_SLAB 16384          // 128*128 (d,h) rows per channel slab
#define WORDS_PER_SLAB 65536         // 128^3 / 32
#define NPACK_TASKS (1u << 19)       // pack: one 32-bit word per thread
#define NBLK2 4096                   // loss: 2^20 tasks (16 voxels each) / 256

__device__ double g_sum;
__device__ double g_cnt;
__device__ unsigned g_done;
__device__ uint4 g_pack[8 * ROWS_PER_SLAB];   // 2 MB bitmask: 1 uint4 = one 128-voxel row

// ---------- 128-bit row ops (bit w = word[w>>5] bit (w&31)) ----------
__device__ __forceinline__ uint4 band(uint4 a, uint4 b) {
    return make_uint4(a.x & b.x, a.y & b.y, a.z & b.z, a.w & b.w);
}
__device__ __forceinline__ uint4 shl1(uint4 a) {   // bit w -> w+1
    return make_uint4(a.x << 1, __funnelshift_l(a.x, a.y, 1),
                      __funnelshift_l(a.y, a.z, 1), __funnelshift_l(a.z, a.w, 1));
}
__device__ __forceinline__ uint4 shr1(uint4 a) {   // bit w -> w-1
    return make_uint4(__funnelshift_r(a.x, a.y, 1), __funnelshift_r(a.y, a.z, 1),
                      __funnelshift_r(a.z, a.w, 1), a.w >> 1);
}
__device__ __forceinline__ uint4 shl2(uint4 a) {
    return make_uint4(a.x << 2, __funnelshift_l(a.x, a.y, 2),
                      __funnelshift_l(a.y, a.z, 2), __funnelshift_l(a.z, a.w, 2));
}
__device__ __forceinline__ uint4 shr2(uint4 a) {
    return make_uint4(__funnelshift_r(a.x, a.y, 2), __funnelshift_r(a.y, a.z, 2),
                      __funnelshift_r(a.z, a.w, 2), a.w >> 2);
}
__device__ __forceinline__ unsigned pick(uint4 v, int s) {
    unsigned lo = (s & 1) ? v.y : v.x;
    unsigned hi = (s & 1) ? v.w : v.z;
    return (s & 2) ? hi : lo;
}

// ---------- Pass 1: bit-pack targets for active channels (+ reset accumulators) ----------
__global__ void __launch_bounds__(256)
pack_kernel(const float* __restrict__ targets,
            const unsigned int* __restrict__ mask)
{
    unsigned j = blockIdx.x * 256u + threadIdx.x;   // word index, < 2^19
    if (j == 0) { g_sum = 0.0; g_cnt = 0.0; g_done = 0u; }

    int slab = j >> 16;                              // 0..7
    int b = slab >> 2;
    int ch = ((slab & 3) << 1) + 1;
    if (mask[b * CDIM + ch] == 0u) return;           // inactive: never read later

    unsigned jin = j & (WORDS_PER_SLAB - 1);
    size_t base = ((size_t)(b * CDIM + ch) << 21) + ((size_t)jin << 5);

    unsigned bits = 0;
    #pragma unroll
    for (int k = 0; k < 8; ++k) {
        float4 v = __ldg((const float4*)(targets + base + k * 4));
        bits |= (v.x > 0.5f ? 1u : 0u) << (4 * k + 0);
        bits |= (v.y > 0.5f ? 1u : 0u) << (4 * k + 1);
        bits |= (v.z > 0.5f ? 1u : 0u) << (4 * k + 2);
        bits |= (v.w > 0.5f ? 1u : 0u) << (4 * k + 3);
    }
    ((unsigned*)g_pack)[j] = bits;
}

// ---------- Pass 2: BCE + erosion-from-bitmask + reduction + fused finalize ----------
// One thread = 16 consecutive voxels of one (d,h) row. Warp = 4 rows.
__global__ void __launch_bounds__(256)
loss_kernel(const float* __restrict__ logits,
            const unsigned int* __restrict__ mask,
            const float* __restrict__ spatial,
            float* __restrict__ out)
{
    unsigned task = blockIdx.x * 256u + threadIdx.x;   // < 2^20
    int slab = task >> 17;
    int b = slab >> 2;
    int ch = ((slab & 3) << 1) + 1;

    float vsum = 0.0f, csum = 0.0f;

    if (mask[b * CDIM + ch] != 0u) {                   // L1-broadcast scalar
        int rr = (task >> 3) & (ROWS_PER_SLAB - 1);    // d*128 + h
        int d = rr >> 7, h = rr & 127;
        int w0 = (task & 7) << 4;                      // 0,16,...,112

        // 8 independent 128-bit loads up front (MLP)
        size_t lix = ((size_t)(b * CDIM + ch) << 21) + ((size_t)rr << 7) + w0;
        unsigned six = ((unsigned)b << 21) + ((unsigned)rr << 7) + w0;
        float4 lg0 = __ldg((const float4*)(logits + lix));
        float4 lg1 = __ldg((const float4*)(logits + lix + 4));
        float4 lg2 = __ldg((const float4*)(logits + lix + 8));
        float4 lg3 = __ldg((const float4*)(logits + lix + 12));
        float4 sm0 = __ldg((const float4*)(spatial + six));
        float4 sm1 = __ldg((const float4*)(spatial + six + 4));
        float4 sm2 = __ldg((const float4*)(spatial + six + 8));
        float4 sm3 = __ldg((const float4*)(spatial + six + 12));

        const uint4* pk = g_pack + slab * ROWS_PER_SLAB;
        uint4 m00 = __ldg(pk + rr);
        unsigned tw = (pick(m00, w0 >> 5) >> (w0 & 31)) & 0xFFFFu;   // 16 target bits

        // double 6-conn erosion == erosion by L1-ball radius 2 (zero-padded)
        unsigned eb = 0;
        if (d >= 2 && d <= 125 && h >= 2 && h <= 125) {
            uint4 R = band(m00, band(__ldg(pk + rr + 256), __ldg(pk + rr - 256)));
            R = band(R, band(__ldg(pk + rr + 2),   __ldg(pk + rr - 2)));
            R = band(R, band(__ldg(pk + rr + 129), __ldg(pk + rr + 127)));
            R = band(R, band(__ldg(pk + rr - 127), __ldg(pk + rr - 129)));
            if (R.x | R.y | R.z | R.w) {               // rarely taken
                uint4 q = band(band(__ldg(pk + rr + 128), __ldg(pk + rr - 128)),
                               band(__ldg(pk + rr + 1),   __ldg(pk + rr - 1)));
                uint4 u = band(m00, q);
                uint4 e = band(band(R, u), band(shl1(u), shr1(u)));
                e = band(e, band(shl2(m00), shr2(m00)));
                eb = (pick(e, w0 >> 5) >> (w0 & 31)) & 0xFFFFu;
            }
        }
        unsigned bbits = tw & ~eb;                     // boundary bits

        const float4 lgs[4] = {lg0, lg1, lg2, lg3};
        const float4 sms[4] = {sm0, sm1, sm2, sm3};
        #pragma unroll
        for (int g = 0; g < 4; ++g) {
            #pragma unroll
            for (int k = 0; k < 4; ++k) {
                int kk = g * 4 + k;
                float l = (k == 0) ? lgs[g].x : (k == 1) ? lgs[g].y : (k == 2) ? lgs[g].z : lgs[g].w;
                float s = (k == 0) ? sms[g].x : (k == 1) ? sms[g].y : (k == 2) ? sms[g].z : sms[g].w;
                unsigned tb = (tw >> kk) & 1u;
                // max(l,0) - l*t == max(sflip, 0) with sflip = t ? -l : l
                float sflip = __uint_as_float(__float_as_uint(l) ^ (tb << 31));
                float u = __expf(-fabsf(l));
                float bce = fmaxf(sflip, 0.0f) + __logf(1.0f + u);
                float wgt = ((bbits >> kk) & 1u) ? 5.0f : 1.0f;
                vsum += bce * wgt * s;
                csum += s;
            }
        }
    }

    // warp reduce
    #pragma unroll
    for (int off = 16; off > 0; off >>= 1) {
        vsum += __shfl_down_sync(0xFFFFFFFFu, vsum, off);
        csum += __shfl_down_sync(0xFFFFFFFFu, csum, off);
    }
    __shared__ float s_v[8], s_c[8];
    int lane = threadIdx.x & 31, wid = threadIdx.x >> 5;
    if (lane == 0) { s_v[wid] = vsum; s_c[wid] = csum; }
    __syncthreads();
    if (wid == 0) {
        vsum = (lane < 8) ? s_v[lane] : 0.0f;
        csum = (lane < 8) ? s_c[lane] : 0.0f;
        #pragma unroll
        for (int off = 4; off > 0; off >>= 1) {
            vsum += __shfl_down_sync(0xFFFFFFFFu, vsum, off);
            csum += __shfl_down_sync(0xFFFFFFFFu, csum, off);
        }
        if (lane == 0) {
            if (vsum != 0.0f) atomicAdd(&g_sum, (double)vsum);
            if (csum != 0.0f) atomicAdd(&g_cnt, (double)csum);
            __threadfence();
            unsigned ticket = atomicAdd(&g_done, 1u);
            if (ticket == NBLK2 - 1u) {              // last block finalizes
                double n = g_cnt;
                double s = g_sum;
                out[0] = (n > 0.0) ? (float)(s / (n > 1.0 ? n : 1.0)) : 0.0f;
            }
        }
    }
}

extern "C" void kernel_launch(void* const* d_in, const int* in_sizes, int n_in,
                              void* d_out, int out_size) {
    const float*        logits  = (const float*)d_in[0];
    const float*        targets = (const float*)d_in[1];
    const unsigned int* mask    = (const unsigned int*)d_in[2];
    const float*        spatial = (const float*)d_in[3];
    float*              out     = (float*)d_out;

    pack_kernel<<<NPACK_TASKS / 256, 256>>>(targets, mask);
    loss_kernel<<<NBLK2, 256>>>(logits, mask, spatial, out);
}

// round 9
// speedup vs baseline: 1.2500x; 1.2500x over previous
#include <cuda_runtime.h>
#include <cuda_bf16.h>

#define SDIM 128
#define CDIM 8
#define ROWS_PER_SLAB 16384          // 128*128 (d,h) rows per channel slab
#define NPACK_TASKS (1u << 19)       // pack: one 32-bit word per thread
#define NERODE (1u << 17)            // erode: one row per thread (8 slabs * 16384)
#define NBLK2 4096                   // loss: 2^20 tasks (16 voxels each) / 256

__device__ double g_sum;
__device__ double g_cnt;
__device__ unsigned g_done;
__device__ uint4 g_pack[8 * ROWS_PER_SLAB];   // 2 MB targets bitmask (1 uint4 = 128-voxel row)
__device__ uint4 g_er[8 * ROWS_PER_SLAB];     // 2 MB eroded bitmask

// ---------- 128-bit row ops ----------
__device__ __forceinline__ uint4 band(uint4 a, uint4 b) {
    return make_uint4(a.x & b.x, a.y & b.y, a.z & b.z, a.w & b.w);
}
__device__ __forceinline__ uint4 shl1(uint4 a) {   // bit w -> w+1 (zero-fill == zero pad)
    return make_uint4(a.x << 1, __funnelshift_l(a.x, a.y, 1),
                      __funnelshift_l(a.y, a.z, 1), __funnelshift_l(a.z, a.w, 1));
}
__device__ __forceinline__ uint4 shr1(uint4 a) {   // bit w -> w-1
    return make_uint4(__funnelshift_r(a.x, a.y, 1), __funnelshift_r(a.y, a.z, 1),
                      __funnelshift_r(a.z, a.w, 1), a.w >> 1);
}
__device__ __forceinline__ uint4 shl2(uint4 a) {
    return make_uint4(a.x << 2, __funnelshift_l(a.x, a.y, 2),
                      __funnelshift_l(a.y, a.z, 2), __funnelshift_l(a.z, a.w, 2));
}
__device__ __forceinline__ uint4 shr2(uint4 a) {
    return make_uint4(__funnelshift_r(a.x, a.y, 2), __funnelshift_r(a.y, a.z, 2),
                      __funnelshift_r(a.z, a.w, 2), a.w >> 2);
}
__device__ __forceinline__ unsigned pick(uint4 v, int s) {
    unsigned lo = (s & 1) ? v.y : v.x;
    unsigned hi = (s & 1) ? v.w : v.z;
    return (s & 2) ? hi : lo;
}

// ---------- Pass 1: bit-pack targets for active channels (+ reset accumulators) ----------
__global__ void __launch_bounds__(256)
pack_kernel(const float* __restrict__ targets,
            const unsigned int* __restrict__ mask)
{
    unsigned j = blockIdx.x * 256u + threadIdx.x;   // word index, < 2^19
    if (j == 0) { g_sum = 0.0; g_cnt = 0.0; g_done = 0u; }

    int slab = j >> 16;                              // 0..7
    int b = slab >> 2;
    int ch = ((slab & 3) << 1) + 1;
    if (mask[b * CDIM + ch] == 0u) return;           // inactive: never read later

    unsigned jin = j & ((1u << 16) - 1);
    size_t base = ((size_t)(b * CDIM + ch) << 21) + ((size_t)jin << 5);

    unsigned bits = 0;
    #pragma unroll
    for (int k = 0; k < 8; ++k) {
        float4 v = __ldg((const float4*)(targets + base + k * 4));
        bits |= (v.x > 0.5f ? 1u : 0u) << (4 * k + 0);
        bits |= (v.y > 0.5f ? 1u : 0u) << (4 * k + 1);
        bits |= (v.z > 0.5f ? 1u : 0u) << (4 * k + 2);
        bits |= (v.w > 0.5f ? 1u : 0u) << (4 * k + 3);
    }
    ((unsigned*)g_pack)[j] = bits;
}

// ---------- Pass 1.5: double 6-conn erosion of the bitmask (one row per thread) ----------
// eroded = erosion by L1-ball radius 2 (zero-padded). w-direction handled by
// zero-filling shifts; d/h border rows (within 2 of an edge) are identically 0.
__global__ void __launch_bounds__(256)
erode_kernel(const unsigned int* __restrict__ mask)
{
    unsigned j = blockIdx.x * 256u + threadIdx.x;    // < 2^17
    int slab = j >> 14;
    int b = slab >> 2;
    int ch = ((slab & 3) << 1) + 1;
    if (mask[b * CDIM + ch] == 0u) return;

    int rr = j & (ROWS_PER_SLAB - 1);
    int d = rr >> 7, h = rr & 127;

    uint4 e = make_uint4(0, 0, 0, 0);
    if (d >= 2 && d <= 125 && h >= 2 && h <= 125) {
        const uint4* pk = g_pack + slab * ROWS_PER_SLAB;
        uint4 m00 = __ldg(pk + rr);
        uint4 a0 = __ldg(pk + rr + 256), a1 = __ldg(pk + rr - 256);
        uint4 a2 = __ldg(pk + rr + 2),   a3 = __ldg(pk + rr - 2);
        uint4 a4 = __ldg(pk + rr + 129), a5 = __ldg(pk + rr + 127);
        uint4 a6 = __ldg(pk + rr - 127), a7 = __ldg(pk + rr - 129);
        uint4 a8 = __ldg(pk + rr + 128), a9 = __ldg(pk + rr - 128);
        uint4 aA = __ldg(pk + rr + 1),   aB = __ldg(pk + rr - 1);

        uint4 R = band(band(band(a0, a1), band(a2, a3)),
                       band(band(a4, a5), band(a6, a7)));
        uint4 q = band(band(a8, a9), band(aA, aB));
        uint4 u = band(m00, q);
        e = band(band(band(R, m00), u), band(shl1(u), shr1(u)));
        e = band(e, band(shl2(m00), shr2(m00)));
    }
    g_er[slab * ROWS_PER_SLAB + rr] = e;
}

// ---------- Pass 2: BCE + weights + reduction + fused finalize ----------
// One thread = 16 consecutive voxels of one (d,h) row.
__global__ void __launch_bounds__(256)
loss_kernel(const float* __restrict__ logits,
            const unsigned int* __restrict__ mask,
            const float* __restrict__ spatial,
            float* __restrict__ out)
{
    unsigned task = blockIdx.x * 256u + threadIdx.x;   // < 2^20
    int slab = task >> 17;
    int b = slab >> 2;
    int ch = ((slab & 3) << 1) + 1;

    float vsum = 0.0f, csum = 0.0f;

    if (mask[b * CDIM + ch] != 0u) {                   // L1-broadcast scalar
        int rr = (task >> 3) & (ROWS_PER_SLAB - 1);    // d*128 + h
        int w0 = (task & 7) << 4;                      // 0,16,...,112

        // 10 independent loads issued up front
        size_t lix = ((size_t)(b * CDIM + ch) << 21) + ((size_t)rr << 7) + w0;
        unsigned six = ((unsigned)b << 21) + ((unsigned)rr << 7) + w0;
        float4 lg0 = __ldg((const float4*)(logits + lix));
        float4 lg1 = __ldg((const float4*)(logits + lix + 4));
        float4 lg2 = __ldg((const float4*)(logits + lix + 8));
        float4 lg3 = __ldg((const float4*)(logits + lix + 12));
        float4 sm0 = __ldg((const float4*)(spatial + six));
        float4 sm1 = __ldg((const float4*)(spatial + six + 4));
        float4 sm2 = __ldg((const float4*)(spatial + six + 8));
        float4 sm3 = __ldg((const float4*)(spatial + six + 12));
        uint4 m00 = __ldg(g_pack + slab * ROWS_PER_SLAB + rr);
        uint4 e00 = __ldg(g_er   + slab * ROWS_PER_SLAB + rr);

        unsigned tw = (pick(m00, w0 >> 5) >> (w0 & 31)) & 0xFFFFu;
        unsigned eb = (pick(e00, w0 >> 5) >> (w0 & 31)) & 0xFFFFu;
        unsigned bbits = tw & ~eb;                     // boundary bits

        const float4 lgs[4] = {lg0, lg1, lg2, lg3};
        const float4 sms[4] = {sm0, sm1, sm2, sm3};
        #pragma unroll
        for (int g = 0; g < 4; ++g) {
            #pragma unroll
            for (int k = 0; k < 4; ++k) {
                int kk = g * 4 + k;
                float l = (k == 0) ? lgs[g].x : (k == 1) ? lgs[g].y : (k == 2) ? lgs[g].z : lgs[g].w;
                float s = (k == 0) ? sms[g].x : (k == 1) ? sms[g].y : (k == 2) ? sms[g].z : sms[g].w;
                unsigned tb = (tw >> kk) & 1u;
                // max(l,0) - l*t == max(sflip, 0) with sflip = t ? -l : l
                float sflip = __uint_as_float(__float_as_uint(l) ^ (tb << 31));
                float u = __expf(-fabsf(l));
                float bce = fmaxf(sflip, 0.0f) + __logf(1.0f + u);
                float wgt = ((bbits >> kk) & 1u) ? 5.0f : 1.0f;
                vsum += bce * wgt * s;
                csum += s;
            }
        }
    }

    // warp reduce
    #pragma unroll
    for (int off = 16; off > 0; off >>= 1) {
        vsum += __shfl_down_sync(0xFFFFFFFFu, vsum, off);
        csum += __shfl_down_sync(0xFFFFFFFFu, csum, off);
    }
    __shared__ float s_v[8], s_c[8];
    int lane = threadIdx.x & 31, wid = threadIdx.x >> 5;
    if (lane == 0) { s_v[wid] = vsum; s_c[wid] = csum; }
    __syncthreads();
    if (wid == 0) {
        vsum = (lane < 8) ? s_v[lane] : 0.0f;
        csum = (lane < 8) ? s_c[lane] : 0.0f;
        #pragma unroll
        for (int off = 4; off > 0; off >>= 1) {
            vsum += __shfl_down_sync(0xFFFFFFFFu, vsum, off);
            csum += __shfl_down_sync(0xFFFFFFFFu, csum, off);
        }
        if (lane == 0) {
            if (vsum != 0.0f) atomicAdd(&g_sum, (double)vsum);
            if (csum != 0.0f) atomicAdd(&g_cnt, (double)csum);
            __threadfence();
            unsigned ticket = atomicAdd(&g_done, 1u);
            if (ticket == NBLK2 - 1u) {              // last block finalizes
                double n = g_cnt;
                double s = g_sum;
                out[0] = (n > 0.0) ? (float)(s / (n > 1.0 ? n : 1.0)) : 0.0f;
            }
        }
    }
}

extern "C" void kernel_launch(void* const* d_in, const int* in_sizes, int n_in,
                              void* d_out, int out_size) {
    const float*        logits  = (const float*)d_in[0];
    const float*        targets = (const float*)d_in[1];
    const unsigned int* mask    = (const unsigned int*)d_in[2];
    const float*        spatial = (const float*)d_in[3];
    float*              out     = (float*)d_out;

    pack_kernel<<<NPACK_TASKS / 256, 256>>>(targets, mask);
    erode_kernel<<<NERODE / 256, 256>>>(mask);
    loss_kernel<<<NBLK2, 256>>>(logits, mask, spatial, out);
}